// round 5
// baseline (speedup 1.0000x reference)
#include <cuda_runtime.h>

// SConv2d majority-gate conv, s-domain math.
// R4: split the 27-channel tree across 3 threads (t-subtrees of 9 channels),
//     768-thread blocks -> 48 warps/SM (was 15.6). Partials exchanged via
//     smem aliased over the x tile.

#define C_IN 27
#define NOC 27
#define HH 32
#define WW 32
#define TILE_H 8
#define SM_ROWS (TILE_H + 2)      // 10
#define SM_W 34
#define SM_CH (SM_ROWS * SM_W)    // 340
#define OCG 3                      // ocs per block
#define WPAD 12                    // padded weights per (oc,c)
#define NPX 256                    // pixels per block
#define NTHR (NPX * 3)             // 768

__device__ __forceinline__ float maj3s(float a, float b, float c) {
    float p = a * b;
    float t = a + b;
    float q = fmaf(-2.0f, p, t);   // a+b-2ab  (imm-FFMA, rt=1)
    return fmaf(q, c, p);          // ab + (a+b-2ab)c
}

__global__ __launch_bounds__(NTHR, 2) void sconv_kernel(const float* __restrict__ x,
                                                        const float* __restrict__ w,
                                                        float* __restrict__ out) {
    __shared__ float xs[C_IN * SM_CH];            // 36720 B (aliased as partials later)
    __shared__ float wsm[OCG * C_IN * WPAD];      // 3888 B

    int b = blockIdx.x;
    int ocg  = b % (NOC / OCG);       // 0..8
    int tile = (b / (NOC / OCG)) & 3; // 0..3
    int n    = b / (4 * (NOC / OCG)); // 0..7
    int h0 = tile * TILE_H;
    int oc0 = ocg * OCG;

    int tid = threadIdx.x;
    int px  = tid & (NPX - 1);        // pixel 0..255
    int cg  = tid >> 8;               // channel group 0..2 (9 channels each)
    int wcol = px & 31;
    int hl   = px >> 5;

    // ---- stage weights: 3 ocs x 27 ch x 9, pre-scaled by 0.5, stride 12
    for (int idx = tid; idx < OCG * C_IN * 9; idx += NTHR) {
        int ocl = idx / (C_IN * 9);
        int rem = idx - ocl * (C_IN * 9);
        int c = rem / 9;
        wsm[(ocl * C_IN + c) * WPAD + (rem - c * 9)] =
            0.5f * w[(oc0 + ocl) * (C_IN * 9) + rem];
    }

    // ---- stage x tile interior (coalesced), borders = -1
    const float* xn = x + (size_t)n * C_IN * HH * WW;
    for (int idx = tid; idx < C_IN * SM_ROWS * 32; idx += NTHR) {
        int rowid = idx >> 5;
        int col   = idx & 31;
        int c = rowid / SM_ROWS;
        int r = rowid - c * SM_ROWS;
        int gh = h0 + r - 1;
        float v = -1.0f;
        if ((unsigned)gh < HH)
            v = xn[(c << 10) + (gh << 5) + col];
        xs[c * SM_CH + r * SM_W + col + 1] = v;
    }
    for (int idx = tid; idx < C_IN * SM_ROWS; idx += NTHR) {
        xs[idx * SM_W + 0] = -1.0f;
        xs[idx * SM_W + SM_W - 1] = -1.0f;
    }
    __syncthreads();

    // ---- each thread: 9 channels [9*cg, 9*cg+9), 3 ocs -> 3 t-subtree roots
    const float* xbase = &xs[hl * SM_W + wcol];
    int c0 = 9 * cg;

    float tpart[OCG];
    float vbuf[OCG][3], ubuf[OCG][3];

    #pragma unroll
    for (int cl = 0; cl < 9; cl++) {
        int c = c0 + cl;
        float xw[9];
        #pragma unroll
        for (int kh = 0; kh < 3; kh++)
            #pragma unroll
            for (int kw = 0; kw < 3; kw++)
                xw[kh * 3 + kw] = xbase[c * SM_CH + kh * SM_W + kw];

        #pragma unroll
        for (int o = 0; o < OCG; o++) {
            const float4* wp = (const float4*)&wsm[(o * C_IN + c) * WPAD];
            float4 wa = wp[0];
            float4 wb = wp[1];
            float w8 = wsm[(o * C_IN + c) * WPAD + 8];
            float wk[9] = {wa.x, wa.y, wa.z, wa.w, wb.x, wb.y, wb.z, wb.w, w8};
            float rkh[3];
            #pragma unroll
            for (int kh = 0; kh < 3; kh++) {
                float s0 = fmaf(xw[kh * 3 + 0], wk[kh * 3 + 0], 0.5f);
                float s1 = fmaf(xw[kh * 3 + 1], wk[kh * 3 + 1], 0.5f);
                float s2 = fmaf(xw[kh * 3 + 2], wk[kh * 3 + 2], 0.5f);
                rkh[kh] = maj3s(s0, s1, s2);
            }
            vbuf[o][cl % 3] = maj3s(rkh[0], rkh[1], rkh[2]);
        }

        if (cl % 3 == 2) {
            #pragma unroll
            for (int o = 0; o < OCG; o++)
                ubuf[o][cl / 3] = maj3s(vbuf[o][0], vbuf[o][1], vbuf[o][2]);
        }
    }
    #pragma unroll
    for (int o = 0; o < OCG; o++)
        tpart[o] = maj3s(ubuf[o][0], ubuf[o][1], ubuf[o][2]);

    // ---- exchange partials via smem aliased over xs (all xs reads are done)
    __syncthreads();
    float* part = xs;   // layout: part[(cg*OCG + o) * NPX + px]
    #pragma unroll
    for (int o = 0; o < OCG; o++)
        part[(cg * OCG + o) * NPX + px] = tpart[o];
    __syncthreads();

    // ---- thread (px, cg) finalizes oc = cg
    int o = cg;
    float t0 = part[(0 * OCG + o) * NPX + px];
    float t1 = part[(1 * OCG + o) * NPX + px];
    float t2 = part[(2 * OCG + o) * NPX + px];
    float rr = maj3s(t0, t1, t2);
    float y = fmaf(2.0f, rr, -1.0f);

    int hg = h0 + hl;
    out[(((size_t)n * NOC + (oc0 + o)) * HH + hg) * WW + wcol] = y;
}

extern "C" void kernel_launch(void* const* d_in, const int* in_sizes, int n_in,
                              void* d_out, int out_size) {
    const float* x = (const float*)d_in[0];     // (8,27,32,32) fp32
    const float* w = (const float*)d_in[1];     // (27,27,3,3) fp32
    float* out = (float*)d_out;                 // (8,27,32,32) fp32

    dim3 grid(8 * 4 * (NOC / OCG));   // 288 blocks x 768 threads
    sconv_kernel<<<grid, NTHR>>>(x, w, out);
}